// round 1
// baseline (speedup 1.0000x reference)
#include <cuda_runtime.h>
#include <cuda_bf16.h>
#include <math.h>

// NT-Xent loss, B=4096, D=256 (D hardcoded), N = 2B = 8192.
// Pipeline:
//   1) normalize_kernel: zn[r] = z[r] / max(||z[r]||, 1e-8); also zeros denom.
//   2) sim_kernel: upper-triangular 128x128 tiles of sim = zn zn^T, accumulates
//      exp(2*sim) into row denominators (and column denominators via symmetry).
//   3) loss_kernel: per-row loss = log(denom - exp(2*self)) - 2*pos.
//   4) reduce_kernel: deterministic single-block sum -> out[0] = total/(2B).

#define DIM 256
#define MAXN 8192

__device__ float g_zn[MAXN * DIM];
__device__ float g_denom[MAXN];
__device__ float g_loss[MAXN];

// ---------------------------------------------------------------------------
// 1) Normalize: one warp per row. Also zero g_denom.
// ---------------------------------------------------------------------------
__global__ void normalize_kernel(const float* __restrict__ zi,
                                 const float* __restrict__ zj,
                                 int B, int N) {
    int tid  = threadIdx.x;
    int warp = tid >> 5;
    int lane = tid & 31;
    int row  = blockIdx.x * 8 + warp;

    // zero denominators
    int gtid = blockIdx.x * blockDim.x + tid;
    if (gtid < N) g_denom[gtid] = 0.0f;

    if (row >= N) return;
    const float* src = (row < B) ? (zi + (size_t)row * DIM)
                                 : (zj + (size_t)(row - B) * DIM);
    // each lane: 8 floats (2 float4)
    float4 v0 = *reinterpret_cast<const float4*>(src + lane * 4);
    float4 v1 = *reinterpret_cast<const float4*>(src + 128 + lane * 4);
    float ss = v0.x * v0.x + v0.y * v0.y + v0.z * v0.z + v0.w * v0.w
             + v1.x * v1.x + v1.y * v1.y + v1.z * v1.z + v1.w * v1.w;
#pragma unroll
    for (int off = 16; off > 0; off >>= 1)
        ss += __shfl_xor_sync(0xFFFFFFFF, ss, off);
    float inv = 1.0f / fmaxf(sqrtf(ss), 1e-8f);
    float* dst = g_zn + (size_t)row * DIM;
    v0.x *= inv; v0.y *= inv; v0.z *= inv; v0.w *= inv;
    v1.x *= inv; v1.y *= inv; v1.z *= inv; v1.w *= inv;
    *reinterpret_cast<float4*>(dst + lane * 4)       = v0;
    *reinterpret_cast<float4*>(dst + 128 + lane * 4) = v1;
}

// ---------------------------------------------------------------------------
// 2) Gram-tile kernel: 128x128 tile per block, 256 threads, 8x8 micro-tile.
//    Only tiles with bn >= bm are computed (symmetry); off-diagonal tiles
//    contribute exp sums to both row and column denominators.
// ---------------------------------------------------------------------------
#define BK 32
#define PAD 132   // 128 + 4 pad to spread smem bank use

__global__ __launch_bounds__(256, 2)
void sim_kernel(int N) {
    int bm = blockIdx.y;
    int bn = blockIdx.x;
    if (bn < bm) return;

    __shared__ float As[BK][PAD];
    __shared__ float Bs[BK][PAD];
    __shared__ float rowsum[128];
    __shared__ float colsum[128];

    int tid = threadIdx.x;
    int tx  = tid & 15;   // 0..15 (col group)
    int ty  = tid >> 4;   // 0..15 (row group)

    int m0 = bm * 128;
    int n0 = bn * 128;

    float acc[2][2][4][4];
#pragma unroll
    for (int i = 0; i < 2; i++)
#pragma unroll
        for (int j = 0; j < 2; j++)
#pragma unroll
            for (int a = 0; a < 4; a++)
#pragma unroll
                for (int b = 0; b < 4; b++)
                    acc[i][j][a][b] = 0.0f;

    for (int kt = 0; kt < DIM; kt += BK) {
        // load 128x32 A-tile and B-tile (transposed to [k][row] in smem)
#pragma unroll
        for (int i = 0; i < 4; i++) {
            int idx = tid + 256 * i;        // 0..1023
            int row = idx >> 3;             // 0..127
            int k4  = idx & 7;              // float4 index in k-chunk
            float4 va = *reinterpret_cast<const float4*>(
                g_zn + (size_t)(m0 + row) * DIM + kt + k4 * 4);
            As[k4 * 4 + 0][row] = va.x;
            As[k4 * 4 + 1][row] = va.y;
            As[k4 * 4 + 2][row] = va.z;
            As[k4 * 4 + 3][row] = va.w;
            float4 vb = *reinterpret_cast<const float4*>(
                g_zn + (size_t)(n0 + row) * DIM + kt + k4 * 4);
            Bs[k4 * 4 + 0][row] = vb.x;
            Bs[k4 * 4 + 1][row] = vb.y;
            Bs[k4 * 4 + 2][row] = vb.z;
            Bs[k4 * 4 + 3][row] = vb.w;
        }
        __syncthreads();

#pragma unroll
        for (int k = 0; k < BK; k++) {
            float4 a0 = *reinterpret_cast<const float4*>(&As[k][ty * 4]);
            float4 a1 = *reinterpret_cast<const float4*>(&As[k][ty * 4 + 64]);
            float4 b0 = *reinterpret_cast<const float4*>(&Bs[k][tx * 4]);
            float4 b1 = *reinterpret_cast<const float4*>(&Bs[k][tx * 4 + 64]);
            float av[2][4] = {{a0.x, a0.y, a0.z, a0.w}, {a1.x, a1.y, a1.z, a1.w}};
            float bv[2][4] = {{b0.x, b0.y, b0.z, b0.w}, {b1.x, b1.y, b1.z, b1.w}};
#pragma unroll
            for (int i = 0; i < 2; i++)
#pragma unroll
                for (int j = 0; j < 2; j++)
#pragma unroll
                    for (int a = 0; a < 4; a++)
#pragma unroll
                        for (int b = 0; b < 4; b++)
                            acc[i][j][a][b] += av[i][a] * bv[j][b];
        }
        __syncthreads();
    }

    // epilogue: exp(2*sim), accumulate row sums (and col sums if off-diagonal)
    if (tid < 128) { rowsum[tid] = 0.0f; colsum[tid] = 0.0f; }
    __syncthreads();

    bool diag = (bm == bn);
#pragma unroll
    for (int i = 0; i < 2; i++) {
#pragma unroll
        for (int a = 0; a < 4; a++) {
            float rs = 0.0f;
            float cs_local[2][4];
#pragma unroll
            for (int j = 0; j < 2; j++)
#pragma unroll
                for (int b = 0; b < 4; b++) {
                    float e = __expf(2.0f * acc[i][j][a][b]);
                    rs += e;
                    cs_local[j][b] = e;
                }
            atomicAdd(&rowsum[ty * 4 + i * 64 + a], rs);
            if (!diag) {
#pragma unroll
                for (int j = 0; j < 2; j++)
#pragma unroll
                    for (int b = 0; b < 4; b++)
                        atomicAdd(&colsum[tx * 4 + j * 64 + b], cs_local[j][b]);
            }
        }
    }
    __syncthreads();

    if (tid < 128) {
        atomicAdd(&g_denom[m0 + tid], rowsum[tid]);
        if (!diag) atomicAdd(&g_denom[n0 + tid], colsum[tid]);
    }
}

// ---------------------------------------------------------------------------
// 3) Per-row loss: warp per row. loss = log(denom - exp(2*self)) - 2*pos.
// ---------------------------------------------------------------------------
__global__ void loss_kernel(int B, int N) {
    int tid  = threadIdx.x;
    int warp = tid >> 5;
    int lane = tid & 31;
    int row  = blockIdx.x * 8 + warp;
    if (row >= N) return;

    int partner = (row < B) ? row + B : row - B;
    const float* a = g_zn + (size_t)row * DIM;
    const float* p = g_zn + (size_t)partner * DIM;

    float selfdot = 0.0f, posdot = 0.0f;
#pragma unroll
    for (int i = 0; i < 2; i++) {
        float4 va = *reinterpret_cast<const float4*>(a + lane * 8 + i * 4);
        float4 vp = *reinterpret_cast<const float4*>(p + lane * 8 + i * 4);
        selfdot += va.x * va.x + va.y * va.y + va.z * va.z + va.w * va.w;
        posdot  += va.x * vp.x + va.y * vp.y + va.z * vp.z + va.w * vp.w;
    }
#pragma unroll
    for (int off = 16; off > 0; off >>= 1) {
        selfdot += __shfl_xor_sync(0xFFFFFFFF, selfdot, off);
        posdot  += __shfl_xor_sync(0xFFFFFFFF, posdot, off);
    }
    if (lane == 0) {
        float denom = g_denom[row] - expf(2.0f * selfdot);
        g_loss[row] = logf(denom) - 2.0f * posdot;
    }
}

// ---------------------------------------------------------------------------
// 4) Deterministic final reduction.
// ---------------------------------------------------------------------------
__global__ void reduce_kernel(int N, float* out) {
    __shared__ float sh[1024];
    int tid = threadIdx.x;
    float s = 0.0f;
    for (int i = tid; i < N; i += 1024) s += g_loss[i];
    sh[tid] = s;
    __syncthreads();
#pragma unroll
    for (int off = 512; off > 0; off >>= 1) {
        if (tid < off) sh[tid] += sh[tid + off];
        __syncthreads();
    }
    if (tid == 0) out[0] = sh[0] / (float)N;
}

// ---------------------------------------------------------------------------
extern "C" void kernel_launch(void* const* d_in, const int* in_sizes, int n_in,
                              void* d_out, int out_size) {
    const float* zi = (const float*)d_in[0];
    const float* zj = (const float*)d_in[1];
    int B = in_sizes[0] / DIM;     // 4096
    int N = 2 * B;                 // 8192

    normalize_kernel<<<(N + 7) / 8, 256>>>(zi, zj, B, N);

    dim3 grid(N / 128, N / 128);
    sim_kernel<<<grid, 256>>>(N);

    loss_kernel<<<(N + 7) / 8, 256>>>(B, N);
    reduce_kernel<<<1, 1024>>>(N, (float*)d_out);
}

// round 3
// speedup vs baseline: 5.4716x; 5.4716x over previous
#include <cuda_runtime.h>
#include <cuda_bf16.h>
#include <math.h>
#include <stdint.h>

// NT-Xent loss, B=4096, D=256, N=8192.
//  1) normalize_kernel: zn = z/||z|| stored bf16; zeros g_denom.
//  2) sim_kernel: upper-triangular 128x128 tiles of zn zn^T via mma.sync
//     (bf16 HMMA). Epilogue: exp(2*sim), diagonal zeroed, row sums ->
//     g_denom[m], col sums -> g_denom[n] (symmetry credit).
//  3) loss_kernel: exact fp32 positives from raw inputs; log(denom) - 2*pos.
//  4) reduce_kernel: deterministic single-block mean.

#define DIM 256
#define MAXN 8192

__device__ __nv_bfloat16 g_zn[MAXN * DIM];
__device__ float g_denom[MAXN];
__device__ float g_loss[MAXN];

__device__ __forceinline__ uint32_t smem_u32(const void* p) {
    uint32_t a;
    asm("{ .reg .u64 t; cvta.to.shared.u64 t, %1; cvt.u32.u64 %0, t; }"
        : "=r"(a) : "l"(p));
    return a;
}

__device__ __forceinline__ void ldsm_x4(uint32_t* r, uint32_t addr) {
    asm volatile("ldmatrix.sync.aligned.m8n8.x4.shared.b16 {%0,%1,%2,%3}, [%4];"
                 : "=r"(r[0]), "=r"(r[1]), "=r"(r[2]), "=r"(r[3]) : "r"(addr));
}

__device__ __forceinline__ void mma16816(float* c, const uint32_t* a,
                                         const uint32_t* b) {
    asm volatile(
        "mma.sync.aligned.m16n8k16.row.col.f32.bf16.bf16.f32 "
        "{%0,%1,%2,%3}, {%4,%5,%6,%7}, {%8,%9}, {%0,%1,%2,%3};"
        : "+f"(c[0]), "+f"(c[1]), "+f"(c[2]), "+f"(c[3])
        : "r"(a[0]), "r"(a[1]), "r"(a[2]), "r"(a[3]), "r"(b[0]), "r"(b[1]));
}

// ---------------------------------------------------------------------------
// 1) Normalize -> bf16, zero denominators.
// ---------------------------------------------------------------------------
__global__ void normalize_kernel(const float* __restrict__ zi,
                                 const float* __restrict__ zj,
                                 int B, int N) {
    int tid  = threadIdx.x;
    int warp = tid >> 5;
    int lane = tid & 31;
    int row  = blockIdx.x * 8 + warp;

    int gtid = blockIdx.x * blockDim.x + tid;
    if (gtid < N) g_denom[gtid] = 0.0f;
    if (row >= N) return;

    const float* src = (row < B) ? (zi + (size_t)row * DIM)
                                 : (zj + (size_t)(row - B) * DIM);
    float4 v0 = *reinterpret_cast<const float4*>(src + lane * 8);
    float4 v1 = *reinterpret_cast<const float4*>(src + lane * 8 + 4);
    float ss = v0.x*v0.x + v0.y*v0.y + v0.z*v0.z + v0.w*v0.w
             + v1.x*v1.x + v1.y*v1.y + v1.z*v1.z + v1.w*v1.w;
#pragma unroll
    for (int off = 16; off > 0; off >>= 1)
        ss += __shfl_xor_sync(0xFFFFFFFF, ss, off);
    float inv = 1.0f / fmaxf(sqrtf(ss), 1e-8f);

    __nv_bfloat16 h[8];
    h[0] = __float2bfloat16(v0.x * inv); h[1] = __float2bfloat16(v0.y * inv);
    h[2] = __float2bfloat16(v0.z * inv); h[3] = __float2bfloat16(v0.w * inv);
    h[4] = __float2bfloat16(v1.x * inv); h[5] = __float2bfloat16(v1.y * inv);
    h[6] = __float2bfloat16(v1.z * inv); h[7] = __float2bfloat16(v1.w * inv);
    *reinterpret_cast<uint4*>(g_zn + (size_t)row * DIM + lane * 8) =
        *reinterpret_cast<uint4*>(h);
}

// ---------------------------------------------------------------------------
// 2) HMMA Gram-tile kernel. 128x128 tile per block (bn >= bm), 8 warps
//    arranged 4(M) x 2(N): warp tile 32x64. K chunks of 64 in smem,
//    XOR-16B-unit swizzle, ldmatrix.x4 fragment loads.
// ---------------------------------------------------------------------------
#define BK 64

__global__ __launch_bounds__(256, 2) void sim_kernel() {
    int bm = blockIdx.y, bn = blockIdx.x;
    if (bn < bm) return;

    __shared__ __align__(16) __nv_bfloat16 sA[128 * BK];
    __shared__ __align__(16) __nv_bfloat16 sB[128 * BK];
    __shared__ float rowsum[128];
    __shared__ float colsum[128];

    int tid  = threadIdx.x;
    int wid  = tid >> 5;
    int lane = tid & 31;
    int warp_m = wid & 3;     // 0..3 -> rows 32*warp_m
    int warp_n = wid >> 2;    // 0..1 -> cols 64*warp_n
    int m0 = bm * 128, n0 = bn * 128;
    bool diag = (bm == bn);

    if (tid < 128) { rowsum[tid] = 0.0f; colsum[tid] = 0.0f; }

    uint32_t sAb = smem_u32(sA);
    uint32_t sBb = smem_u32(sB);

    float acc[2][8][4];
#pragma unroll
    for (int mt = 0; mt < 2; mt++)
#pragma unroll
        for (int nt = 0; nt < 8; nt++)
#pragma unroll
            for (int q = 0; q < 4; q++) acc[mt][nt][q] = 0.0f;

    // precompute ldmatrix lane-address components
    int a_row = warp_m * 32 + (lane & 15);        // + mt*16
    int a_ub  = lane >> 4;                        // + ks*2
    int b_row = warp_n * 64 + ((lane >> 4) & 1) * 8 + (lane & 7);  // + p*16
    int b_ub  = (lane >> 3) & 1;                  // + ks*2

    for (int ch = 0; ch < 4; ch++) {
        int kc0 = ch * BK;
        // fill smem: 128 rows x 8 units of 16B each, swizzled
        __syncthreads();
#pragma unroll
        for (int it = 0; it < 4; it++) {
            int u = tid + it * 256;               // 0..1023
            int row = u >> 3;
            int kc  = u & 7;
            uint32_t sw = (uint32_t)row * 128u + (uint32_t)((kc ^ (row & 7)) << 4);
            uint4 va = *reinterpret_cast<const uint4*>(
                g_zn + (size_t)(m0 + row) * DIM + kc0 + kc * 8);
            uint4 vb = *reinterpret_cast<const uint4*>(
                g_zn + (size_t)(n0 + row) * DIM + kc0 + kc * 8);
            *reinterpret_cast<uint4*>((char*)sA + sw) = va;
            *reinterpret_cast<uint4*>((char*)sB + sw) = vb;
        }
        __syncthreads();

#pragma unroll
        for (int ks = 0; ks < 4; ks++) {
            uint32_t ra[2][4];
#pragma unroll
            for (int mt = 0; mt < 2; mt++) {
                int row = a_row + mt * 16;
                int u   = ks * 2 + a_ub;
                ldsm_x4(ra[mt], sAb + row * 128 + ((u ^ (row & 7)) << 4));
            }
#pragma unroll
            for (int p = 0; p < 4; p++) {
                uint32_t rb[4];
                int row = b_row + p * 16;
                int u   = ks * 2 + b_ub;
                ldsm_x4(rb, sBb + row * 128 + ((u ^ (row & 7)) << 4));
#pragma unroll
                for (int mt = 0; mt < 2; mt++) {
                    mma16816(acc[mt][p * 2 + 0], ra[mt], rb + 0);
                    mma16816(acc[mt][p * 2 + 1], ra[mt], rb + 2);
                }
            }
        }
    }

    // ---------------- epilogue ----------------
    __syncthreads();
    int r0 = lane >> 2;            // 0..7
    int c0 = (lane & 3) * 2;       // 0,2,4,6

    float rs[2][2] = {{0, 0}, {0, 0}};   // [mt][row half]
    float cs[8][2] = {};                 // [nt][n pair] summed over this thread's rows

#pragma unroll
    for (int mt = 0; mt < 2; mt++) {
#pragma unroll
        for (int nt = 0; nt < 8; nt++) {
            float e[4];
#pragma unroll
            for (int q = 0; q < 4; q++) {
                int ml = warp_m * 32 + mt * 16 + r0 + (q >> 1) * 8;
                int nl = warp_n * 64 + nt * 8 + c0 + (q & 1);
                float v = __expf(2.0f * acc[mt][nt][q]);
                if (diag && ml == nl) v = 0.0f;
                e[q] = v;
            }
            rs[mt][0] += e[0] + e[1];
            rs[mt][1] += e[2] + e[3];
            cs[nt][0] += e[0] + e[2];
            cs[nt][1] += e[1] + e[3];
        }
    }
    // row sums: reduce over lanes sharing r0 (xor 1,2)
#pragma unroll
    for (int mt = 0; mt < 2; mt++)
#pragma unroll
        for (int h = 0; h < 2; h++) {
            float v = rs[mt][h];
            v += __shfl_xor_sync(0xFFFFFFFFu, v, 1);
            v += __shfl_xor_sync(0xFFFFFFFFu, v, 2);
            if ((lane & 3) == 0)
                atomicAdd(&rowsum[warp_m * 32 + mt * 16 + r0 + h * 8], v);
        }
    // col sums: reduce over lanes sharing c0 (xor 4,8,16)
#pragma unroll
    for (int nt = 0; nt < 8; nt++)
#pragma unroll
        for (int h = 0; h < 2; h++) {
            float v = cs[nt][h];
            v += __shfl_xor_sync(0xFFFFFFFFu, v, 4);
            v += __shfl_xor_sync(0xFFFFFFFFu, v, 8);
            v += __shfl_xor_sync(0xFFFFFFFFu, v, 16);
            if (lane < 4)
                atomicAdd(&colsum[warp_n * 64 + nt * 8 + c0 + h], v);
        }
    __syncthreads();

    if (tid < 128) {
        atomicAdd(&g_denom[m0 + tid], rowsum[tid]);
        if (!diag) atomicAdd(&g_denom[n0 + tid], colsum[tid]);
    }
}

// ---------------------------------------------------------------------------
// 3) Per-row loss: exact fp32 positives from raw inputs.
// ---------------------------------------------------------------------------
__global__ void loss_kernel(const float* __restrict__ zi,
                            const float* __restrict__ zj,
                            int B, int N) {
    int tid  = threadIdx.x;
    int warp = tid >> 5;
    int lane = tid & 31;
    int row  = blockIdx.x * 8 + warp;
    if (row >= N) return;

    const float* a;
    const float* p;
    if (row < B) { a = zi + (size_t)row * DIM;        p = zj + (size_t)row * DIM; }
    else         { a = zj + (size_t)(row - B) * DIM;  p = zi + (size_t)(row - B) * DIM; }

    float na = 0.0f, npv = 0.0f, dot = 0.0f;
#pragma unroll
    for (int i = 0; i < 2; i++) {
        float4 va = *reinterpret_cast<const float4*>(a + lane * 8 + i * 4);
        float4 vp = *reinterpret_cast<const float4*>(p + lane * 8 + i * 4);
        na  += va.x*va.x + va.y*va.y + va.z*va.z + va.w*va.w;
        npv += vp.x*vp.x + vp.y*vp.y + vp.z*vp.z + vp.w*vp.w;
        dot += va.x*vp.x + va.y*vp.y + va.z*vp.z + va.w*vp.w;
    }
#pragma unroll
    for (int off = 16; off > 0; off >>= 1) {
        na  += __shfl_xor_sync(0xFFFFFFFF, na,  off);
        npv += __shfl_xor_sync(0xFFFFFFFF, npv, off);
        dot += __shfl_xor_sync(0xFFFFFFFF, dot, off);
    }
    if (lane == 0) {
        float pos = dot / (fmaxf(sqrtf(na), 1e-8f) * fmaxf(sqrtf(npv), 1e-8f));
        g_loss[row] = logf(g_denom[row]) - 2.0f * pos;
    }
}

// ---------------------------------------------------------------------------
// 4) Deterministic final reduction.
// ---------------------------------------------------------------------------
__global__ void reduce_kernel(int N, float* out) {
    __shared__ float sh[1024];
    int tid = threadIdx.x;
    float s = 0.0f;
    for (int i = tid; i < N; i += 1024) s += g_loss[i];
    sh[tid] = s;
    __syncthreads();
#pragma unroll
    for (int off = 512; off > 0; off >>= 1) {
        if (tid < off) sh[tid] += sh[tid + off];
        __syncthreads();
    }
    if (tid == 0) out[0] = sh[0] / (float)N;
}

// ---------------------------------------------------------------------------
extern "C" void kernel_launch(void* const* d_in, const int* in_sizes, int n_in,
                              void* d_out, int out_size) {
    const float* zi = (const float*)d_in[0];
    const float* zj = (const float*)d_in[1];
    int B = in_sizes[0] / DIM;     // 4096
    int N = 2 * B;                 // 8192

    normalize_kernel<<<(N + 7) / 8, 256>>>(zi, zj, B, N);

    dim3 grid(N / 128, N / 128);
    sim_kernel<<<grid, 256>>>();

    loss_kernel<<<(N + 7) / 8, 256>>>(zi, zj, B, N);
    reduce_kernel<<<1, 1024>>>(N, (float*)d_out);
}

// round 4
// speedup vs baseline: 6.2969x; 1.1508x over previous
#include <cuda_runtime.h>
#include <cuda_bf16.h>
#include <math.h>
#include <stdint.h>

// NT-Xent loss, B=4096, D=256, N=8192.
//  1) normalize_kernel: zn = z/||z|| stored bf16; zeros g_denom.
//  2) sim_kernel: strict-upper-triangular 128x128 tiles of zn zn^T via
//     mma.sync bf16, 2x2 warps of 64x64, cp.async double-buffered K loop.
//     Epilogue: exp(2*sim), diag zeroed, row sums -> g_denom[m],
//     col sums -> g_denom[n] (symmetry credit).
//  3) loss_kernel: exact fp32 positives from raw inputs; log(denom) - 2*pos.
//  4) reduce_kernel: deterministic single-block mean.

#define DIM 256
#define MAXN 8192
#define BK 64

__device__ __nv_bfloat16 g_zn[MAXN * DIM];
__device__ float g_denom[MAXN];
__device__ float g_loss[MAXN];

__device__ __forceinline__ uint32_t smem_u32(const void* p) {
    uint32_t a;
    asm("{ .reg .u64 t; cvta.to.shared.u64 t, %1; cvt.u32.u64 %0, t; }"
        : "=r"(a) : "l"(p));
    return a;
}

__device__ __forceinline__ void ldsm_x4(uint32_t* r, uint32_t addr) {
    asm volatile("ldmatrix.sync.aligned.m8n8.x4.shared.b16 {%0,%1,%2,%3}, [%4];"
                 : "=r"(r[0]), "=r"(r[1]), "=r"(r[2]), "=r"(r[3]) : "r"(addr));
}

__device__ __forceinline__ void mma16816(float* c, const uint32_t* a,
                                         const uint32_t* b) {
    asm volatile(
        "mma.sync.aligned.m16n8k16.row.col.f32.bf16.bf16.f32 "
        "{%0,%1,%2,%3}, {%4,%5,%6,%7}, {%8,%9}, {%0,%1,%2,%3};"
        : "+f"(c[0]), "+f"(c[1]), "+f"(c[2]), "+f"(c[3])
        : "r"(a[0]), "r"(a[1]), "r"(a[2]), "r"(a[3]), "r"(b[0]), "r"(b[1]));
}

__device__ __forceinline__ void cp_async16(uint32_t saddr, uint64_t gaddr) {
    asm volatile("cp.async.cg.shared.global [%0], [%1], 16;"
                 :: "r"(saddr), "l"(gaddr) : "memory");
}
#define CP_COMMIT() asm volatile("cp.async.commit_group;" ::: "memory")
#define CP_WAIT(n)  asm volatile("cp.async.wait_group %0;" :: "n"(n) : "memory")

// ---------------------------------------------------------------------------
// 1) Normalize -> bf16, zero denominators.
// ---------------------------------------------------------------------------
__global__ void normalize_kernel(const float* __restrict__ zi,
                                 const float* __restrict__ zj,
                                 int B, int N) {
    int tid  = threadIdx.x;
    int warp = tid >> 5;
    int lane = tid & 31;
    int row  = blockIdx.x * 8 + warp;

    int gtid = blockIdx.x * blockDim.x + tid;
    if (gtid < N) g_denom[gtid] = 0.0f;
    if (row >= N) return;

    const float* src = (row < B) ? (zi + (size_t)row * DIM)
                                 : (zj + (size_t)(row - B) * DIM);
    float4 v0 = *reinterpret_cast<const float4*>(src + lane * 8);
    float4 v1 = *reinterpret_cast<const float4*>(src + lane * 8 + 4);
    float ss = v0.x*v0.x + v0.y*v0.y + v0.z*v0.z + v0.w*v0.w
             + v1.x*v1.x + v1.y*v1.y + v1.z*v1.z + v1.w*v1.w;
#pragma unroll
    for (int off = 16; off > 0; off >>= 1)
        ss += __shfl_xor_sync(0xFFFFFFFF, ss, off);
    float inv = 1.0f / fmaxf(sqrtf(ss), 1e-8f);

    __nv_bfloat16 h[8];
    h[0] = __float2bfloat16(v0.x * inv); h[1] = __float2bfloat16(v0.y * inv);
    h[2] = __float2bfloat16(v0.z * inv); h[3] = __float2bfloat16(v0.w * inv);
    h[4] = __float2bfloat16(v1.x * inv); h[5] = __float2bfloat16(v1.y * inv);
    h[6] = __float2bfloat16(v1.z * inv); h[7] = __float2bfloat16(v1.w * inv);
    *reinterpret_cast<uint4*>(g_zn + (size_t)row * DIM + lane * 8) =
        *reinterpret_cast<uint4*>(h);
}

// ---------------------------------------------------------------------------
// 2) HMMA Gram-tile kernel. 128x128 tile per block, triangular grid
//    (bn >= bm). 4 warps in 2x2, warp tile 64x64. K chunks of 64,
//    cp.async double buffer, XOR-16B swizzle.
//    Dyn smem: 2 bufs x (A 16KB + B 16KB) = 64KB.
// ---------------------------------------------------------------------------
__global__ __launch_bounds__(128, 2) void sim_kernel(int nt) {
    // decode triangular linear index -> (bm, bn), bn >= bm
    int t = blockIdx.x;
    float f = 2.0f * (float)nt + 1.0f;
    int bm = (int)((f - sqrtf(f * f - 8.0f * (float)t)) * 0.5f);
    while ((bm + 1) * nt - (((bm + 1) * bm) >> 1) <= t) bm++;
    while (bm * nt - ((bm * (bm - 1)) >> 1) > t) bm--;
    int bn = bm + (t - (bm * nt - ((bm * (bm - 1)) >> 1)));

    extern __shared__ char dsm[];
    __shared__ float rowsum[128];
    __shared__ float colsum[128];

    int tid  = threadIdx.x;
    int wid  = tid >> 5;
    int lane = tid & 31;
    int warp_m = wid & 1;
    int warp_n = wid >> 1;
    int m0 = bm * 128, n0 = bn * 128;
    bool diag = (bm == bn);

    if (tid < 128) { rowsum[tid] = 0.0f; colsum[tid] = 0.0f; }

    uint32_t sbase = smem_u32(dsm);
    uint64_t gbase = (uint64_t)__cvta_generic_to_global(g_zn);

    float acc[4][8][4];
#pragma unroll
    for (int mt = 0; mt < 4; mt++)
#pragma unroll
        for (int ntk = 0; ntk < 8; ntk++)
#pragma unroll
            for (int q = 0; q < 4; q++) acc[mt][ntk][q] = 0.0f;

    // ldmatrix lane-address components
    int a_row = warp_m * 64 + (lane & 15);                         // + mt*16
    int a_ub  = lane >> 4;                                         // + ks*2
    int b_row = warp_n * 64 + ((lane >> 4) & 1) * 8 + (lane & 7);  // + p*16
    int b_ub  = (lane >> 3) & 1;                                   // + ks*2
    int a_sw = a_row & 7, b_sw = b_row & 7;

    // prefetch helper (chunk ch into buffer buf)
    auto prefetch = [&](int ch, int buf) {
        uint32_t sb = sbase + (uint32_t)buf * 32768u;
        int kc0 = ch * BK;
#pragma unroll
        for (int it = 0; it < 8; it++) {
            int u = tid + it * 128;              // 0..1023
            int row = u >> 3;
            int kc  = u & 7;
            uint32_t sw = (uint32_t)row * 128u + (uint32_t)((kc ^ (row & 7)) << 4);
            cp_async16(sb + sw,
                       gbase + ((uint64_t)(m0 + row) * DIM + kc0 + kc * 8) * 2u);
            cp_async16(sb + 16384u + sw,
                       gbase + ((uint64_t)(n0 + row) * DIM + kc0 + kc * 8) * 2u);
        }
        CP_COMMIT();
    };

    prefetch(0, 0);

    for (int ch = 0; ch < 4; ch++) {
        int buf = ch & 1;
        if (ch + 1 < 4) {
            prefetch(ch + 1, (ch + 1) & 1);
            CP_WAIT(1);
        } else {
            CP_WAIT(0);
        }
        __syncthreads();

        uint32_t sA = sbase + (uint32_t)buf * 32768u;
        uint32_t sB = sA + 16384u;

#pragma unroll
        for (int ks = 0; ks < 4; ks++) {
            uint32_t ra[4][4];
#pragma unroll
            for (int mt = 0; mt < 4; mt++) {
                int row = a_row + mt * 16;
                int u   = ks * 2 + a_ub;
                ldsm_x4(ra[mt], sA + row * 128 + ((u ^ a_sw) << 4));
            }
#pragma unroll
            for (int p = 0; p < 4; p++) {
                uint32_t rb[4];
                int row = b_row + p * 16;
                int u   = ks * 2 + b_ub;
                ldsm_x4(rb, sB + row * 128 + ((u ^ b_sw) << 4));
#pragma unroll
                for (int mt = 0; mt < 4; mt++) {
                    mma16816(acc[mt][p * 2 + 0], ra[mt], rb + 0);
                    mma16816(acc[mt][p * 2 + 1], ra[mt], rb + 2);
                }
            }
        }
        __syncthreads();
    }

    // ---------------- epilogue ----------------
    int r0 = lane >> 2;            // 0..7
    int c0 = (lane & 3) * 2;       // 0,2,4,6

    float rs[4][2] = {};           // [mt][row half]
    float cs[8][2] = {};           // [nt][col pair]

#pragma unroll
    for (int mt = 0; mt < 4; mt++) {
#pragma unroll
        for (int ntk = 0; ntk < 8; ntk++) {
            float e[4];
#pragma unroll
            for (int q = 0; q < 4; q++) {
                int ml = warp_m * 64 + mt * 16 + r0 + (q >> 1) * 8;
                int nl = warp_n * 64 + ntk * 8 + c0 + (q & 1);
                float v = __expf(2.0f * acc[mt][ntk][q]);
                if (diag && ml == nl) v = 0.0f;
                e[q] = v;
            }
            rs[mt][0] += e[0] + e[1];
            rs[mt][1] += e[2] + e[3];
            cs[ntk][0] += e[0] + e[2];
            cs[ntk][1] += e[1] + e[3];
        }
    }
    // row sums: reduce over lanes sharing r0 (xor 1,2)
#pragma unroll
    for (int mt = 0; mt < 4; mt++)
#pragma unroll
        for (int h = 0; h < 2; h++) {
            float v = rs[mt][h];
            v += __shfl_xor_sync(0xFFFFFFFFu, v, 1);
            v += __shfl_xor_sync(0xFFFFFFFFu, v, 2);
            if ((lane & 3) == 0)
                atomicAdd(&rowsum[warp_m * 64 + mt * 16 + r0 + h * 8], v);
        }
    // col sums: reduce over lanes sharing c0 (xor 4,8,16)
#pragma unroll
    for (int ntk = 0; ntk < 8; ntk++)
#pragma unroll
        for (int h = 0; h < 2; h++) {
            float v = cs[ntk][h];
            v += __shfl_xor_sync(0xFFFFFFFFu, v, 4);
            v += __shfl_xor_sync(0xFFFFFFFFu, v, 8);
            v += __shfl_xor_sync(0xFFFFFFFFu, v, 16);
            if (lane < 4)
                atomicAdd(&colsum[warp_n * 64 + ntk * 8 + c0 + h], v);
        }
    __syncthreads();

    if (tid < 128) {
        atomicAdd(&g_denom[m0 + tid], rowsum[tid]);
        if (!diag) atomicAdd(&g_denom[n0 + tid], colsum[tid]);
    }
}

// ---------------------------------------------------------------------------
// 3) Per-row loss: exact fp32 positives from raw inputs.
// ---------------------------------------------------------------------------
__global__ void loss_kernel(const float* __restrict__ zi,
                            const float* __restrict__ zj,
                            int B, int N) {
    int tid  = threadIdx.x;
    int warp = tid >> 5;
    int lane = tid & 31;
    int row  = blockIdx.x * 8 + warp;
    if (row >= N) return;

    const float* a;
    const float* p;
    if (row < B) { a = zi + (size_t)row * DIM;        p = zj + (size_t)row * DIM; }
    else         { a = zj + (size_t)(row - B) * DIM;  p = zi + (size_t)(row - B) * DIM; }

    float na = 0.0f, npv = 0.0f, dot = 0.0f;
#pragma unroll
    for (int i = 0; i < 2; i++) {
        float4 va = *reinterpret_cast<const float4*>(a + lane * 8 + i * 4);
        float4 vp = *reinterpret_cast<const float4*>(p + lane * 8 + i * 4);
        na  += va.x*va.x + va.y*va.y + va.z*va.z + va.w*va.w;
        npv += vp.x*vp.x + vp.y*vp.y + vp.z*vp.z + vp.w*vp.w;
        dot += va.x*vp.x + va.y*vp.y + va.z*vp.z + va.w*vp.w;
    }
#pragma unroll
    for (int off = 16; off > 0; off >>= 1) {
        na  += __shfl_xor_sync(0xFFFFFFFF, na,  off);
        npv += __shfl_xor_sync(0xFFFFFFFF, npv, off);
        dot += __shfl_xor_sync(0xFFFFFFFF, dot, off);
    }
    if (lane == 0) {
        float pos = dot / (fmaxf(sqrtf(na), 1e-8f) * fmaxf(sqrtf(npv), 1e-8f));
        g_loss[row] = logf(g_denom[row]) - 2.0f * pos;
    }
}

// ---------------------------------------------------------------------------
// 4) Deterministic final reduction.
// ---------------------------------------------------------------------------
__global__ void reduce_kernel(int N, float* out) {
    __shared__ float sh[1024];
    int tid = threadIdx.x;
    float s = 0.0f;
    for (int i = tid; i < N; i += 1024) s += g_loss[i];
    sh[tid] = s;
    __syncthreads();
#pragma unroll
    for (int off = 512; off > 0; off >>= 1) {
        if (tid < off) sh[tid] += sh[tid + off];
        __syncthreads();
    }
    if (tid == 0) out[0] = sh[0] / (float)N;
}

// ---------------------------------------------------------------------------
extern "C" void kernel_launch(void* const* d_in, const int* in_sizes, int n_in,
                              void* d_out, int out_size) {
    const float* zi = (const float*)d_in[0];
    const float* zj = (const float*)d_in[1];
    int B = in_sizes[0] / DIM;     // 4096
    int N = 2 * B;                 // 8192
    int nt = N / 128;              // 64 tile rows
    int ntri = nt * (nt + 1) / 2;  // 2080 triangular tiles

    cudaFuncSetAttribute(sim_kernel,
                         cudaFuncAttributeMaxDynamicSharedMemorySize, 65536);

    normalize_kernel<<<(N + 7) / 8, 256>>>(zi, zj, B, N);
    sim_kernel<<<ntri, 128, 65536>>>(nt);
    loss_kernel<<<(N + 7) / 8, 256>>>(zi, zj, B, N);
    reduce_kernel<<<1, 1024>>>(N, (float*)d_out);
}